// round 4
// baseline (speedup 1.0000x reference)
#include <cuda_runtime.h>
#include <cuda_fp16.h>
#include <cstdint>

// ---------------- problem constants ----------------
#define S_SPEC   4
#define E_ENS    8
#define NPS      12500          // atoms per species
#define AEVD     1008
#define NTILE    64             // atoms per block tile
#define TILES    196            // 12544 / 64
#define NPAD     (TILES * NTILE)  // 12544

// layer dims
#define N1 256
#define N2 192
#define N3 160

// smem strides (halfs)
#define LD1  264
#define LD2  200
#define LD3  168
#define LDA  52
#define LDW1 52
#define LDW23 68

// smem offsets (halfs) — h3 aliases h1 (h1 dead once L2 completes)
#define H1H_OFF 0
#define H1L_OFF (H1H_OFF + NTILE * LD1)       // 16896
#define H2H_OFF (H1L_OFF + NTILE * LD1)       // 33792
#define H2L_OFF (H2H_OFF + NTILE * LD2)       // 46592
#define H3H_OFF H1H_OFF
#define H3L_OFF H1L_OFF
#define SAH_OFF (H2L_OFF + NTILE * LD2)       // 59392
#define SAL_OFF (SAH_OFF + NTILE * LDA)       // 62720
#define SWH_OFF (SAL_OFF + NTILE * LDA)       // 66048
#define SWL_OFF (SWH_OFF + N1 * LDW1)         // 79360
#define SMEM_HALFS (SWL_OFF + N1 * LDW1)      // 92672
#define SMEM_BYTES (SMEM_HALFS * 2)           // 185344

// ---------------- device scratch (static; no runtime alloc) ----------------
__device__ __half g_Agh[(size_t)S_SPEC * NPAD * AEVD];
__device__ __half g_Agl[(size_t)S_SPEC * NPAD * AEVD];
__device__ __half g_W1h[(size_t)S_SPEC * E_ENS * N1 * AEVD];
__device__ __half g_W1l[(size_t)S_SPEC * E_ENS * N1 * AEVD];
__device__ __half g_W2h[(size_t)S_SPEC * E_ENS * N2 * N1];
__device__ __half g_W2l[(size_t)S_SPEC * E_ENS * N2 * N1];
__device__ __half g_W3h[(size_t)S_SPEC * E_ENS * N3 * N2];
__device__ __half g_W3l[(size_t)S_SPEC * E_ENS * N3 * N2];

__device__ __forceinline__ void split_h(float v, __half& hh, __half& hl) {
    hh = __float2half_rn(v);
    hl = __float2half_rn(v - __half2float(hh));
}

// ---------------- prep: gather aev by species, split to fp16 hi/lo ----------------
__global__ void prep_aev_kernel(const float* __restrict__ aev, const int* __restrict__ idx,
                                float* __restrict__ out) {
    if (blockIdx.x == 0 && threadIdx.x == 0) out[0] = 0.f;
    const long total4 = (long)S_SPEC * NPAD * AEVD / 4;
    long stride = (long)gridDim.x * blockDim.x;
    for (long i = (long)blockIdx.x * blockDim.x + threadIdx.x; i < total4; i += stride) {
        long i0 = i * 4;
        int s = (int)(i0 / ((long)NPAD * AEVD));
        long rem = i0 - (long)s * NPAD * AEVD;
        int row = (int)(rem / AEVD);
        int k = (int)(rem % AEVD);
        __half h[4], l[4];
        if (row < NPS) {
            int src = idx[s * NPS + row];
            float4 v = *(const float4*)(aev + (long)src * AEVD + k);
            split_h(v.x, h[0], l[0]); split_h(v.y, h[1], l[1]);
            split_h(v.z, h[2], l[2]); split_h(v.w, h[3], l[3]);
        } else {
            __half z = __float2half(0.f);
            h[0]=h[1]=h[2]=h[3]=z; l[0]=l[1]=l[2]=l[3]=z;
        }
        *(uint2*)(g_Agh + i0) = *(uint2*)h;
        *(uint2*)(g_Agl + i0) = *(uint2*)l;
    }
}

// ---------------- prep: tiled transpose + split weights ----------------
// src: [SE][din][dout] fp32 -> dsth/dstl: [SE][dout][din] fp16
__global__ void transpose_w_kernel(const float* __restrict__ src,
                                   __half* __restrict__ dsth, __half* __restrict__ dstl,
                                   int din, int dout) {
    __shared__ float tile[32][33];
    const int se = blockIdx.z;
    const int k0 = blockIdx.y * 32;
    const int n0 = blockIdx.x * 32;
    const float* s = src + (size_t)se * din * dout;
    __half* dh = dsth + (size_t)se * din * dout;
    __half* dl = dstl + (size_t)se * din * dout;
    const int tx = threadIdx.x, ty = threadIdx.y;
#pragma unroll
    for (int r = ty; r < 32; r += 8) {
        int k = k0 + r, n = n0 + tx;
        tile[r][tx] = (k < din && n < dout) ? s[(size_t)k * dout + n] : 0.f;
    }
    __syncthreads();
#pragma unroll
    for (int r = ty; r < 32; r += 8) {
        int n = n0 + r, k = k0 + tx;
        if (n < dout && k < din) {
            __half hh, hl; split_h(tile[tx][r], hh, hl);
            dh[(size_t)n * din + k] = hh;
            dl[(size_t)n * din + k] = hl;
        }
    }
}

// ---------------- mma helpers ----------------
__device__ __forceinline__ float celu_f(float x) {
    return x > 0.f ? x : (0.1f * __expf(10.f * x) - 0.1f);
}

#define MMA(acc, A0, A1, A2, A3, B0, B1)                                        \
    asm volatile("mma.sync.aligned.m16n8k16.row.col.f32.f16.f16.f32 "           \
                 "{%0,%1,%2,%3}, {%4,%5,%6,%7}, {%8,%9}, {%0,%1,%2,%3};\n"      \
                 : "+f"(acc[0]), "+f"(acc[1]), "+f"(acc[2]), "+f"(acc[3])       \
                 : "r"(A0), "r"(A1), "r"(A2), "r"(A3), "r"(B0), "r"(B1))

// one k16 step with split operands: acc += Ah*Wh + Ah*Wl + Al*Wh
template<int NFR>
__device__ __forceinline__ void mma_tri(const __half* sAh, const __half* sAl, int lda, int m0,
                                        const __half* sWh, const __half* sWl, int ldw, int n0,
                                        int k0, int lane, float (&acc)[2][8][4]) {
    const int g = lane >> 2, t = lane & 3;
    uint32_t bh[NFR][2], bl[NFR][2];
#pragma unroll
    for (int nj = 0; nj < NFR; nj++) {
        int off = (n0 + nj * 8 + g) * ldw + k0 + 2 * t;
        bh[nj][0] = *(const uint32_t*)(sWh + off);
        bh[nj][1] = *(const uint32_t*)(sWh + off + 8);
        bl[nj][0] = *(const uint32_t*)(sWl + off);
        bl[nj][1] = *(const uint32_t*)(sWl + off + 8);
    }
#pragma unroll
    for (int mi = 0; mi < 2; mi++) {
        int off = (m0 + mi * 16 + g) * lda + k0 + 2 * t;
        uint32_t ah0 = *(const uint32_t*)(sAh + off);
        uint32_t ah1 = *(const uint32_t*)(sAh + off + 8 * lda);
        uint32_t ah2 = *(const uint32_t*)(sAh + off + 8);
        uint32_t ah3 = *(const uint32_t*)(sAh + off + 8 * lda + 8);
        uint32_t al0 = *(const uint32_t*)(sAl + off);
        uint32_t al1 = *(const uint32_t*)(sAl + off + 8 * lda);
        uint32_t al2 = *(const uint32_t*)(sAl + off + 8);
        uint32_t al3 = *(const uint32_t*)(sAl + off + 8 * lda + 8);
#pragma unroll
        for (int nj = 0; nj < NFR; nj++) {
            MMA(acc[mi][nj], ah0, ah1, ah2, ah3, bh[nj][0], bh[nj][1]);
            MMA(acc[mi][nj], ah0, ah1, ah2, ah3, bl[nj][0], bl[nj][1]);
            MMA(acc[mi][nj], al0, al1, al2, al3, bh[nj][0], bh[nj][1]);
        }
    }
}

template<int NFR>
__device__ __forceinline__ void zero_acc(float (&acc)[2][8][4]) {
#pragma unroll
    for (int mi = 0; mi < 2; mi++)
#pragma unroll
        for (int nj = 0; nj < NFR; nj++)
#pragma unroll
            for (int q = 0; q < 4; q++) acc[mi][nj][q] = 0.f;
}

template<int NFR>
__device__ __forceinline__ void epilogue_celu(float (&acc)[2][8][4], const float* __restrict__ bias,
                                              int n0, int m0, __half* sOutH, __half* sOutL,
                                              int ldo, int lane) {
    const int g = lane >> 2, t = lane & 3;
#pragma unroll
    for (int nj = 0; nj < NFR; nj++) {
        int n = n0 + nj * 8 + 2 * t;
        float bn0 = bias[n], bn1 = bias[n + 1];
#pragma unroll
        for (int mi = 0; mi < 2; mi++) {
            int r0 = m0 + mi * 16 + g;
            float v00 = celu_f(acc[mi][nj][0] + bn0);
            float v01 = celu_f(acc[mi][nj][1] + bn1);
            float v10 = celu_f(acc[mi][nj][2] + bn0);
            float v11 = celu_f(acc[mi][nj][3] + bn1);
            __half h00, l00, h01, l01, h10, l10, h11, l11;
            split_h(v00, h00, l00); split_h(v01, h01, l01);
            split_h(v10, h10, l10); split_h(v11, h11, l11);
            *(__half2*)(sOutH + r0 * ldo + n)       = __halves2half2(h00, h01);
            *(__half2*)(sOutL + r0 * ldo + n)       = __halves2half2(l00, l01);
            *(__half2*)(sOutH + (r0 + 8) * ldo + n) = __halves2half2(h10, h11);
            *(__half2*)(sOutL + (r0 + 8) * ldo + n) = __halves2half2(l10, l11);
        }
    }
}

// stage one W plane slab [nrows][kt] (global row stride kglob) into smem [nrows][ldw]
__device__ __forceinline__ void stage_w(const __half* __restrict__ gW, int kglob, int k0,
                                        __half* sW, int ldw, int nrows, int kt, int tid) {
    int kp = kt / 2;
    int pairs = nrows * kp;
    for (int q = tid; q < pairs; q += 256) {
        int n = q / kp, kk = q - n * kp;
        *(uint32_t*)(sW + n * ldw + kk * 2) = *(const uint32_t*)(gW + n * kglob + k0 + kk * 2);
    }
}

// ---------------- fused main kernel ----------------
extern "C" __global__ void __launch_bounds__(256, 1)
fused_ensemble_kernel(const float* __restrict__ b1, const float* __restrict__ b2,
                      const float* __restrict__ b3, const float* __restrict__ b4,
                      const float* __restrict__ W4, float* __restrict__ out) {
    extern __shared__ __align__(16) __half smem[];
    __half* h1h = smem + H1H_OFF;  __half* h1l = smem + H1L_OFF;
    __half* h2h = smem + H2H_OFF;  __half* h2l = smem + H2L_OFF;
    __half* h3h = smem + H3H_OFF;  __half* h3l = smem + H3L_OFF;
    __half* sAh = smem + SAH_OFF;  __half* sAl = smem + SAL_OFF;
    __half* sWh = smem + SWH_OFF;  __half* sWl = smem + SWL_OFF;

    const int tile = blockIdx.x, e = blockIdx.y, s = blockIdx.z;
    const int se = s * E_ENS + e;
    const int tid = threadIdx.x;
    const int warp = tid >> 5, lane = tid & 31;
    const int wm = warp >> 2, wn = warp & 3;   // 2 x 4 warp grid
    const int m0 = wm * 32;

    const size_t aoff = (size_t)s * NPAD * AEVD + (size_t)tile * NTILE * AEVD;
    const __half* Agh = g_Agh + aoff;
    const __half* Agl = g_Agl + aoff;
    const __half* W1hp = g_W1h + (size_t)se * N1 * AEVD;
    const __half* W1lp = g_W1l + (size_t)se * N1 * AEVD;
    const __half* W2hp = g_W2h + (size_t)se * N2 * N1;
    const __half* W2lp = g_W2l + (size_t)se * N2 * N1;
    const __half* W3hp = g_W3h + (size_t)se * N3 * N2;
    const __half* W3lp = g_W3l + (size_t)se * N3 * N2;
    const float* b1p = b1 + se * N1;
    const float* b2p = b2 + se * N2;
    const float* b3p = b3 + se * N3;
    const float* W4p = W4 + se * N3;
    const float  b4v = b4[se];

    float acc[2][8][4];

    // ---- layer 1: [64,1008] x [1008,256] ----
    zero_acc<8>(acc);
    for (int k0 = 0; k0 < AEVD; k0 += 48) {
        for (int q = tid; q < NTILE * 12; q += 256) {
            int m = q / 12, kk = q - m * 12;
            size_t src = (size_t)m * AEVD + k0 + kk * 4;
            *(uint2*)(sAh + m * LDA + kk * 4) = *(const uint2*)(Agh + src);
            *(uint2*)(sAl + m * LDA + kk * 4) = *(const uint2*)(Agl + src);
        }
        stage_w(W1hp, AEVD, k0, sWh, LDW1, N1, 48, tid);
        stage_w(W1lp, AEVD, k0, sWl, LDW1, N1, 48, tid);
        __syncthreads();
#pragma unroll
        for (int kq = 0; kq < 3; kq++)
            mma_tri<8>(sAh, sAl, LDA, m0, sWh, sWl, LDW1, wn * 64, kq * 16, lane, acc);
        __syncthreads();
    }
    epilogue_celu<8>(acc, b1p, wn * 64, m0, h1h, h1l, LD1, lane);
    __syncthreads();

    // ---- layer 2: [64,256] x [256,192] ----
    zero_acc<6>(acc);
    for (int k0 = 0; k0 < N1; k0 += 64) {
        stage_w(W2hp, N1, k0, sWh, LDW23, N2, 64, tid);
        stage_w(W2lp, N1, k0, sWl, LDW23, N2, 64, tid);
        __syncthreads();
#pragma unroll
        for (int kq = 0; kq < 4; kq++)
            mma_tri<6>(h1h + k0, h1l + k0, LD1, m0, sWh, sWl, LDW23, wn * 48, kq * 16, lane, acc);
        __syncthreads();
    }
    epilogue_celu<6>(acc, b2p, wn * 48, m0, h2h, h2l, LD2, lane);
    __syncthreads();

    // ---- layer 3: [64,192] x [192,160] ----
    zero_acc<5>(acc);
    for (int k0 = 0; k0 < N2; k0 += 64) {
        stage_w(W3hp, N2, k0, sWh, LDW23, N3, 64, tid);
        stage_w(W3lp, N2, k0, sWl, LDW23, N3, 64, tid);
        __syncthreads();
#pragma unroll
        for (int kq = 0; kq < 4; kq++)
            mma_tri<5>(h2h + k0, h2l + k0, LD2, m0, sWh, sWl, LDW23, wn * 40, kq * 16, lane, acc);
        __syncthreads();
    }
    epilogue_celu<5>(acc, b3p, wn * 40, m0, h3h, h3l, LD3, lane);
    __syncthreads();

    // ---- layer 4: [64,160] x fp32 w4 + masked reduction ----
    {
        int row = tid >> 2;            // 64 rows, 4 threads each
        int q4 = tid & 3;
        int kh = q4 * 40;
        const __half2* hph = (const __half2*)(h3h + row * LD3 + kh);
        const __half2* hpl = (const __half2*)(h3l + row * LD3 + kh);
        const float* wp = W4p + kh;
        float sx = 0.f, sy = 0.f;
#pragma unroll
        for (int k = 0; k < 20; k++) {
            float2 ah = __half22float2(hph[k]);
            float2 al = __half22float2(hpl[k]);
            sx += (ah.x + al.x) * wp[2 * k];
            sy += (ah.y + al.y) * wp[2 * k + 1];
        }
        float d = sx + sy;
        d += __shfl_xor_sync(0xffffffffu, d, 1);
        d += __shfl_xor_sync(0xffffffffu, d, 2);
        float psum = 0.f;
        int gr = tile * NTILE + row;
        if (q4 == 0 && gr < NPS) psum = d + b4v;
#pragma unroll
        for (int off = 16; off; off >>= 1) psum += __shfl_xor_sync(0xffffffffu, psum, off);
        __shared__ float red[8];
        if (lane == 0) red[warp] = psum;
        __syncthreads();
        if (tid == 0) {
            float tot = 0.f;
#pragma unroll
            for (int w = 0; w < 8; w++) tot += red[w];
            atomicAdd(out, 0.125f * tot);   // ensemble mean
        }
    }
}

// ---------------- launch ----------------
extern "C" void kernel_launch(void* const* d_in, const int* in_sizes, int n_in,
                              void* d_out, int out_size) {
    const float *aev = nullptr, *W1 = nullptr, *b1 = nullptr, *W2 = nullptr, *b2 = nullptr;
    const float *W3 = nullptr, *b3 = nullptr, *W4 = nullptr, *b4 = nullptr;
    const int *idx = nullptr;
    int c50k = 0, c5120 = 0;
    for (int i = 0; i < n_in; i++) {
        int sz = in_sizes[i];
        const void* p = d_in[i];
        switch (sz) {
            case 50400000: aev = (const float*)p; break;
            case 50000:    if (c50k++ == 1) idx = (const int*)p;  // species first, idx second
                           break;
            case 8257536:  W1 = (const float*)p; break;
            case 8192:     b1 = (const float*)p; break;
            case 1572864:  W2 = (const float*)p; break;
            case 6144:     b2 = (const float*)p; break;
            case 983040:   W3 = (const float*)p; break;
            case 5120:     if (c5120++ == 0) b3 = (const float*)p; else W4 = (const float*)p; break;
            case 32:       b4 = (const float*)p; break;
            default: break;
        }
    }

    cudaFuncSetAttribute(fused_ensemble_kernel,
                         cudaFuncAttributeMaxDynamicSharedMemorySize, SMEM_BYTES);

    prep_aev_kernel<<<8192, 256>>>(aev, idx, (float*)d_out);

    {
        dim3 blk(32, 8);
        __half *w1h, *w1l, *w2h, *w2l, *w3h, *w3l;
        cudaGetSymbolAddress((void**)&w1h, g_W1h);
        cudaGetSymbolAddress((void**)&w1l, g_W1l);
        cudaGetSymbolAddress((void**)&w2h, g_W2h);
        cudaGetSymbolAddress((void**)&w2l, g_W2l);
        cudaGetSymbolAddress((void**)&w3h, g_W3h);
        cudaGetSymbolAddress((void**)&w3l, g_W3l);
        transpose_w_kernel<<<dim3(N1 / 32, (AEVD + 31) / 32, S_SPEC * E_ENS), blk>>>(W1, w1h, w1l, AEVD, N1);
        transpose_w_kernel<<<dim3(N2 / 32, N1 / 32, S_SPEC * E_ENS), blk>>>(W2, w2h, w2l, N1, N2);
        transpose_w_kernel<<<dim3(N3 / 32, N2 / 32, S_SPEC * E_ENS), blk>>>(W3, w3h, w3l, N2, N3);
    }

    dim3 grid(TILES, E_ENS, S_SPEC);
    fused_ensemble_kernel<<<grid, 256, SMEM_BYTES>>>(b1, b2, b3, b4, W4, (float*)d_out);
}

// round 5
// speedup vs baseline: 2.4286x; 2.4286x over previous
#include <cuda_runtime.h>
#include <cuda_fp16.h>
#include <cstdint>

// ---------------- problem constants ----------------
#define S_SPEC   4
#define E_ENS    8
#define NPS      12500
#define AEVD     1008
#define AEVK     1024            // K padded to 32*32
#define NTILE    64
#define TILES    196
#define NPAD     (TILES * NTILE)  // 12544

#define N1 256
#define N2 192
#define N3 160

// smem strides (halfs)
#define LD1  264
#define LD2  200
#define LD3  168
#define LDW  40                  // KT=32 + 8 pad
#define KT   32

// smem offsets (halfs); h3 aliases h1
#define H1H_OFF 0
#define H1L_OFF (H1H_OFF + NTILE * LD1)       // 16896
#define H2H_OFF (H1L_OFF + NTILE * LD1)       // 33792
#define H2L_OFF (H2H_OFF + NTILE * LD2)       // 46592
#define H3H_OFF H1H_OFF
#define H3L_OFF H1L_OFF
#define SW_OFF  (H2L_OFF + NTILE * LD2)       // 59392
#define SW_STAGE (2 * N1 * LDW)               // 20480 halfs per stage (2 planes)
#define SW_PLANE (N1 * LDW)                   // 10240
#define SA_OFF  (SW_OFF + 2 * SW_STAGE)       // 100352
#define SA_STAGE (2 * NTILE * LDW)            // 5120
#define SA_PLANE (NTILE * LDW)                // 2560
#define SMEM_HALFS (SA_OFF + 2 * SA_STAGE)    // 110592
#define SMEM_BYTES (SMEM_HALFS * 2)           // 221184

// ---------------- device scratch ----------------
__device__ __half g_Agh[(size_t)S_SPEC * NPAD * AEVK];
__device__ __half g_Agl[(size_t)S_SPEC * NPAD * AEVK];
__device__ __half g_W1h[(size_t)S_SPEC * E_ENS * N1 * AEVK];
__device__ __half g_W1l[(size_t)S_SPEC * E_ENS * N1 * AEVK];
__device__ __half g_W2h[(size_t)S_SPEC * E_ENS * N2 * N1];
__device__ __half g_W2l[(size_t)S_SPEC * E_ENS * N2 * N1];
__device__ __half g_W3h[(size_t)S_SPEC * E_ENS * N3 * N2];
__device__ __half g_W3l[(size_t)S_SPEC * E_ENS * N3 * N2];

__device__ __forceinline__ void split_h(float v, __half& hh, __half& hl) {
    hh = __float2half_rn(v);
    hl = __float2half_rn(v - __half2float(hh));
}

// ---------------- cp.async helpers ----------------
__device__ __forceinline__ void cp16(__half* smem_dst, const __half* gsrc) {
    uint32_t s = (uint32_t)__cvta_generic_to_shared(smem_dst);
    asm volatile("cp.async.cg.shared.global [%0], [%1], 16;" :: "r"(s), "l"(gsrc));
}
#define CP_COMMIT() asm volatile("cp.async.commit_group;" ::: "memory")
#define CP_WAIT1()  asm volatile("cp.async.wait_group 1;" ::: "memory")
#define CP_WAIT0()  asm volatile("cp.async.wait_group 0;" ::: "memory")

// ---------------- prep kernels ----------------
__global__ void prep_aev_kernel(const float* __restrict__ aev, const int* __restrict__ idx,
                                float* __restrict__ out) {
    if (blockIdx.x == 0 && threadIdx.x == 0) out[0] = 0.f;
    const long total4 = (long)S_SPEC * NPAD * AEVK / 4;
    long stride = (long)gridDim.x * blockDim.x;
    for (long i = (long)blockIdx.x * blockDim.x + threadIdx.x; i < total4; i += stride) {
        long i0 = i * 4;
        int s = (int)(i0 / ((long)NPAD * AEVK));
        long rem = i0 - (long)s * NPAD * AEVK;
        int row = (int)(rem / AEVK);
        int k = (int)(rem % AEVK);
        __half h[4], l[4];
        if (row < NPS && k < AEVD) {
            int src = idx[s * NPS + row];
            float4 v = *(const float4*)(aev + (long)src * AEVD + k);
            split_h(v.x, h[0], l[0]); split_h(v.y, h[1], l[1]);
            split_h(v.z, h[2], l[2]); split_h(v.w, h[3], l[3]);
        } else {
            __half z = __float2half(0.f);
            h[0]=h[1]=h[2]=h[3]=z; l[0]=l[1]=l[2]=l[3]=z;
        }
        *(uint2*)(g_Agh + i0) = *(uint2*)h;
        *(uint2*)(g_Agl + i0) = *(uint2*)l;
    }
}

// src: [SE][din][dout] fp32 -> dsth/dstl: [SE][dout][dinPad] fp16 (k >= din zero)
__global__ void transpose_w_kernel(const float* __restrict__ src,
                                   __half* __restrict__ dsth, __half* __restrict__ dstl,
                                   int din, int dinPad, int dout) {
    __shared__ float tile[32][33];
    const int se = blockIdx.z;
    const int k0 = blockIdx.y * 32;
    const int n0 = blockIdx.x * 32;
    const float* s = src + (size_t)se * din * dout;
    __half* dh = dsth + (size_t)se * dinPad * dout;
    __half* dl = dstl + (size_t)se * dinPad * dout;
    const int tx = threadIdx.x, ty = threadIdx.y;
#pragma unroll
    for (int r = ty; r < 32; r += 8) {
        int k = k0 + r, n = n0 + tx;
        tile[r][tx] = (k < din && n < dout) ? s[(size_t)k * dout + n] : 0.f;
    }
    __syncthreads();
#pragma unroll
    for (int r = ty; r < 32; r += 8) {
        int n = n0 + r, k = k0 + tx;
        if (n < dout) {
            __half hh, hl; split_h(tile[tx][r], hh, hl);
            dh[(size_t)n * dinPad + k] = hh;
            dl[(size_t)n * dinPad + k] = hl;
        }
    }
}

// ---------------- mma helpers ----------------
__device__ __forceinline__ float celu_f(float x) {
    return x > 0.f ? x : (0.1f * __expf(10.f * x) - 0.1f);
}

#define MMA(acc, A0, A1, A2, A3, B0, B1)                                        \
    asm volatile("mma.sync.aligned.m16n8k16.row.col.f32.f16.f16.f32 "           \
                 "{%0,%1,%2,%3}, {%4,%5,%6,%7}, {%8,%9}, {%0,%1,%2,%3};\n"      \
                 : "+f"(acc[0]), "+f"(acc[1]), "+f"(acc[2]), "+f"(acc[3])       \
                 : "r"(A0), "r"(A1), "r"(A2), "r"(A3), "r"(B0), "r"(B1))

// one k16 step, split operands: acc += Ah*Wh + Ah*Wl + Al*Wh
template<int NFR>
__device__ __forceinline__ void mma_tri(const __half* sAh, const __half* sAl, int lda, int m0,
                                        const __half* sWh, const __half* sWl, int ldw, int n0,
                                        int k0, int lane, float (&acc)[2][8][4]) {
    const int g = lane >> 2, t = lane & 3;
    uint32_t bh[NFR][2], bl[NFR][2];
#pragma unroll
    for (int nj = 0; nj < NFR; nj++) {
        int off = (n0 + nj * 8 + g) * ldw + k0 + 2 * t;
        bh[nj][0] = *(const uint32_t*)(sWh + off);
        bh[nj][1] = *(const uint32_t*)(sWh + off + 8);
        bl[nj][0] = *(const uint32_t*)(sWl + off);
        bl[nj][1] = *(const uint32_t*)(sWl + off + 8);
    }
#pragma unroll
    for (int mi = 0; mi < 2; mi++) {
        int off = (m0 + mi * 16 + g) * lda + k0 + 2 * t;
        uint32_t ah0 = *(const uint32_t*)(sAh + off);
        uint32_t ah1 = *(const uint32_t*)(sAh + off + 8 * lda);
        uint32_t ah2 = *(const uint32_t*)(sAh + off + 8);
        uint32_t ah3 = *(const uint32_t*)(sAh + off + 8 * lda + 8);
        uint32_t al0 = *(const uint32_t*)(sAl + off);
        uint32_t al1 = *(const uint32_t*)(sAl + off + 8 * lda);
        uint32_t al2 = *(const uint32_t*)(sAl + off + 8);
        uint32_t al3 = *(const uint32_t*)(sAl + off + 8 * lda + 8);
#pragma unroll
        for (int nj = 0; nj < NFR; nj++) {
            MMA(acc[mi][nj], ah0, ah1, ah2, ah3, bh[nj][0], bh[nj][1]);
            MMA(acc[mi][nj], ah0, ah1, ah2, ah3, bl[nj][0], bl[nj][1]);
            MMA(acc[mi][nj], al0, al1, al2, al3, bh[nj][0], bh[nj][1]);
        }
    }
}

template<int NFR>
__device__ __forceinline__ void zero_acc(float (&acc)[2][8][4]) {
#pragma unroll
    for (int mi = 0; mi < 2; mi++)
#pragma unroll
        for (int nj = 0; nj < NFR; nj++)
#pragma unroll
            for (int q = 0; q < 4; q++) acc[mi][nj][q] = 0.f;
}

template<int NFR>
__device__ __forceinline__ void epilogue_celu(float (&acc)[2][8][4], const float* __restrict__ bias,
                                              int n0, int m0, __half* sOutH, __half* sOutL,
                                              int ldo, int lane) {
    const int g = lane >> 2, t = lane & 3;
#pragma unroll
    for (int nj = 0; nj < NFR; nj++) {
        int n = n0 + nj * 8 + 2 * t;
        float bn0 = bias[n], bn1 = bias[n + 1];
#pragma unroll
        for (int mi = 0; mi < 2; mi++) {
            int r0 = m0 + mi * 16 + g;
            float v00 = celu_f(acc[mi][nj][0] + bn0);
            float v01 = celu_f(acc[mi][nj][1] + bn1);
            float v10 = celu_f(acc[mi][nj][2] + bn0);
            float v11 = celu_f(acc[mi][nj][3] + bn1);
            __half h00, l00, h01, l01, h10, l10, h11, l11;
            split_h(v00, h00, l00); split_h(v01, h01, l01);
            split_h(v10, h10, l10); split_h(v11, h11, l11);
            *(__half2*)(sOutH + r0 * ldo + n)       = __halves2half2(h00, h01);
            *(__half2*)(sOutL + r0 * ldo + n)       = __halves2half2(l00, l01);
            *(__half2*)(sOutH + (r0 + 8) * ldo + n) = __halves2half2(h10, h11);
            *(__half2*)(sOutL + (r0 + 8) * ldo + n) = __halves2half2(l10, l11);
        }
    }
}

// ---- async staging ----
// L1: W (256 rows) + A (64 rows), both planes, KT=32 (4 x 16B per row)
__device__ __forceinline__ void stage_l1(__half* smem, int stage, int k0,
                                         const __half* gWh, const __half* gWl,
                                         const __half* gAh, const __half* gAl, int tid) {
    __half* sw = smem + SW_OFF + stage * SW_STAGE;
    __half* sa = smem + SA_OFF + stage * SA_STAGE;
#pragma unroll
    for (int c = tid; c < 2560; c += 256) {
        if (c < 2048) {
            int plane = c >> 10, rr = (c & 1023) >> 2, cc = c & 3;
            const __half* src = (plane ? gWl : gWh) + (size_t)rr * AEVK + k0 + cc * 8;
            cp16(sw + plane * SW_PLANE + rr * LDW + cc * 8, src);
        } else {
            int c2 = c - 2048;
            int plane = c2 >> 8, rr = (c2 & 255) >> 2, cc = c2 & 3;
            const __half* src = (plane ? gAl : gAh) + (size_t)rr * AEVK + k0 + cc * 8;
            cp16(sa + plane * SA_PLANE + rr * LDW + cc * 8, src);
        }
    }
}

// L2/L3: W only (ROWS rows), both planes
template<int ROWS>
__device__ __forceinline__ void stage_w23(__half* smem, int stage, int k0, int kglob,
                                          const __half* gWh, const __half* gWl, int tid) {
    __half* sw = smem + SW_OFF + stage * SW_STAGE;
    const int per_plane = ROWS * 4;
#pragma unroll
    for (int c = tid; c < 2 * per_plane; c += 256) {
        int plane = c / per_plane, r2 = c % per_plane;
        int rr = r2 >> 2, cc = r2 & 3;
        const __half* src = (plane ? gWl : gWh) + (size_t)rr * kglob + k0 + cc * 8;
        cp16(sw + plane * SW_PLANE + rr * LDW + cc * 8, src);
    }
}

// ---------------- fused main kernel ----------------
extern "C" __global__ void __launch_bounds__(256, 1)
fused_ensemble_kernel(const float* __restrict__ b1, const float* __restrict__ b2,
                      const float* __restrict__ b3, const float* __restrict__ b4,
                      const float* __restrict__ W4, float* __restrict__ out) {
    extern __shared__ __align__(16) __half smem[];
    __half* h1h = smem + H1H_OFF;  __half* h1l = smem + H1L_OFF;
    __half* h2h = smem + H2H_OFF;  __half* h2l = smem + H2L_OFF;
    __half* h3h = smem + H3H_OFF;  __half* h3l = smem + H3L_OFF;

    const int tile = blockIdx.x, e = blockIdx.y, s = blockIdx.z;
    const int se = s * E_ENS + e;
    const int tid = threadIdx.x;
    const int warp = tid >> 5, lane = tid & 31;
    const int wm = warp >> 2, wn = warp & 3;   // 2 x 4 warp grid
    const int m0 = wm * 32;

    const size_t aoff = (size_t)s * NPAD * AEVK + (size_t)tile * NTILE * AEVK;
    const __half* Agh = g_Agh + aoff;
    const __half* Agl = g_Agl + aoff;
    const __half* W1hp = g_W1h + (size_t)se * N1 * AEVK;
    const __half* W1lp = g_W1l + (size_t)se * N1 * AEVK;
    const __half* W2hp = g_W2h + (size_t)se * N2 * N1;
    const __half* W2lp = g_W2l + (size_t)se * N2 * N1;
    const __half* W3hp = g_W3h + (size_t)se * N3 * N2;
    const __half* W3lp = g_W3l + (size_t)se * N3 * N2;
    const float* b1p = b1 + se * N1;
    const float* b2p = b2 + se * N2;
    const float* b3p = b3 + se * N3;
    const float* W4p = W4 + se * N3;
    const float  b4v = b4[se];

    float acc[2][8][4];

    // ================= layer 1: [64,1024] x [1024,256], 32 slabs =================
    const int S1 = AEVK / KT;   // 32
    stage_l1(smem, 0, 0, W1hp, W1lp, Agh, Agl, tid); CP_COMMIT();
    stage_l1(smem, 1, KT, W1hp, W1lp, Agh, Agl, tid); CP_COMMIT();
    zero_acc<8>(acc);
    for (int i = 0; i < S1; i++) {
        if (i + 1 < S1) { CP_WAIT1(); } else { CP_WAIT0(); }
        __syncthreads();
        const __half* sw = smem + SW_OFF + (i & 1) * SW_STAGE;
        const __half* sa = smem + SA_OFF + (i & 1) * SA_STAGE;
#pragma unroll
        for (int kq = 0; kq < 2; kq++)
            mma_tri<8>(sa, sa + SA_PLANE, LDW, m0, sw, sw + SW_PLANE, LDW, wn * 64,
                       kq * 16, lane, acc);
        __syncthreads();
        if (i + 2 < S1) { stage_l1(smem, i & 1, (i + 2) * KT, W1hp, W1lp, Agh, Agl, tid); CP_COMMIT(); }
    }
    epilogue_celu<8>(acc, b1p, wn * 64, m0, h1h, h1l, LD1, lane);
    // prefetch L2 slabs 0,1 (W buffers are free after L1's final tail sync)
    stage_w23<N2>(smem, 0, 0, N1, W2hp, W2lp, tid); CP_COMMIT();
    stage_w23<N2>(smem, 1, KT, N1, W2hp, W2lp, tid); CP_COMMIT();

    // ================= layer 2: [64,256] x [256,192], 8 slabs =================
    const int S2 = N1 / KT;   // 8
    zero_acc<6>(acc);
    for (int i = 0; i < S2; i++) {
        if (i + 1 < S2) { CP_WAIT1(); } else { CP_WAIT0(); }
        __syncthreads();   // also publishes h1 on i==0
        const __half* sw = smem + SW_OFF + (i & 1) * SW_STAGE;
#pragma unroll
        for (int kq = 0; kq < 2; kq++)
            mma_tri<6>(h1h + i * KT, h1l + i * KT, LD1, m0, sw, sw + SW_PLANE, LDW, wn * 48,
                       kq * 16, lane, acc);
        __syncthreads();
        if (i + 2 < S2) { stage_w23<N2>(smem, i & 1, (i + 2) * KT, N1, W2hp, W2lp, tid); CP_COMMIT(); }
    }
    epilogue_celu<6>(acc, b2p, wn * 48, m0, h2h, h2l, LD2, lane);
    stage_w23<N3>(smem, 0, 0, N2, W3hp, W3lp, tid); CP_COMMIT();
    stage_w23<N3>(smem, 1, KT, N2, W3hp, W3lp, tid); CP_COMMIT();

    // ================= layer 3: [64,192] x [192,160], 6 slabs =================
    const int S3 = N2 / KT;   // 6
    zero_acc<5>(acc);
    for (int i = 0; i < S3; i++) {
        if (i + 1 < S3) { CP_WAIT1(); } else { CP_WAIT0(); }
        __syncthreads();
        const __half* sw = smem + SW_OFF + (i & 1) * SW_STAGE;
#pragma unroll
        for (int kq = 0; kq < 2; kq++)
            mma_tri<5>(h2h + i * KT, h2l + i * KT, LD2, m0, sw, sw + SW_PLANE, LDW, wn * 40,
                       kq * 16, lane, acc);
        __syncthreads();
        if (i + 2 < S3) { stage_w23<N3>(smem, i & 1, (i + 2) * KT, N2, W3hp, W3lp, tid); CP_COMMIT(); }
    }
    epilogue_celu<5>(acc, b3p, wn * 40, m0, h3h, h3l, LD3, lane);
    __syncthreads();

    // ================= layer 4: [64,160] x fp32 w4 + masked reduction =================
    {
        int row = tid >> 2;            // 64 rows, 4 threads each
        int q4 = tid & 3;
        int kh = q4 * 40;
        const __half2* hph = (const __half2*)(h3h + row * LD3 + kh);
        const __half2* hpl = (const __half2*)(h3l + row * LD3 + kh);
        const float* wp = W4p + kh;
        float sx = 0.f, sy = 0.f;
#pragma unroll
        for (int k = 0; k < 20; k++) {
            float2 ah = __half22float2(hph[k]);
            float2 al = __half22float2(hpl[k]);
            sx += (ah.x + al.x) * wp[2 * k];
            sy += (ah.y + al.y) * wp[2 * k + 1];
        }
        float d = sx + sy;
        d += __shfl_xor_sync(0xffffffffu, d, 1);
        d += __shfl_xor_sync(0xffffffffu, d, 2);
        float psum = 0.f;
        int gr = tile * NTILE + row;
        if (q4 == 0 && gr < NPS) psum = d + b4v;
#pragma unroll
        for (int off = 16; off; off >>= 1) psum += __shfl_xor_sync(0xffffffffu, psum, off);
        __shared__ float red[8];
        if (lane == 0) red[warp] = psum;
        __syncthreads();
        if (tid == 0) {
            float tot = 0.f;
#pragma unroll
            for (int w = 0; w < 8; w++) tot += red[w];
            atomicAdd(out, 0.125f * tot);   // ensemble mean
        }
    }
}

// ---------------- launch ----------------
extern "C" void kernel_launch(void* const* d_in, const int* in_sizes, int n_in,
                              void* d_out, int out_size) {
    const float *aev = nullptr, *W1 = nullptr, *b1 = nullptr, *W2 = nullptr, *b2 = nullptr;
    const float *W3 = nullptr, *b3 = nullptr, *W4 = nullptr, *b4 = nullptr;
    const int *idx = nullptr;
    int c50k = 0, c5120 = 0;
    for (int i = 0; i < n_in; i++) {
        int sz = in_sizes[i];
        const void* p = d_in[i];
        switch (sz) {
            case 50400000: aev = (const float*)p; break;
            case 50000:    if (c50k++ == 1) idx = (const int*)p; break;
            case 8257536:  W1 = (const float*)p; break;
            case 8192:     b1 = (const float*)p; break;
            case 1572864:  W2 = (const float*)p; break;
            case 6144:     b2 = (const float*)p; break;
            case 983040:   W3 = (const float*)p; break;
            case 5120:     if (c5120++ == 0) b3 = (const float*)p; else W4 = (const float*)p; break;
            case 32:       b4 = (const float*)p; break;
            default: break;
        }
    }

    cudaFuncSetAttribute(fused_ensemble_kernel,
                         cudaFuncAttributeMaxDynamicSharedMemorySize, SMEM_BYTES);

    prep_aev_kernel<<<8192, 256>>>(aev, idx, (float*)d_out);

    {
        dim3 blk(32, 8);
        __half *w1h, *w1l, *w2h, *w2l, *w3h, *w3l;
        cudaGetSymbolAddress((void**)&w1h, g_W1h);
        cudaGetSymbolAddress((void**)&w1l, g_W1l);
        cudaGetSymbolAddress((void**)&w2h, g_W2h);
        cudaGetSymbolAddress((void**)&w2l, g_W2l);
        cudaGetSymbolAddress((void**)&w3h, g_W3h);
        cudaGetSymbolAddress((void**)&w3l, g_W3l);
        transpose_w_kernel<<<dim3(N1 / 32, AEVK / 32, S_SPEC * E_ENS), blk>>>(W1, w1h, w1l, AEVD, AEVK, N1);
        transpose_w_kernel<<<dim3(N2 / 32, N1 / 32, S_SPEC * E_ENS), blk>>>(W2, w2h, w2l, N1, N1, N2);
        transpose_w_kernel<<<dim3(N3 / 32, N2 / 32, S_SPEC * E_ENS), blk>>>(W3, w3h, w3l, N2, N2, N3);
    }

    dim3 grid(TILES, E_ENS, S_SPEC);
    fused_ensemble_kernel<<<grid, 256, SMEM_BYTES>>>(b1, b2, b3, b4, W4, (float*)d_out);
}